// round 2
// baseline (speedup 1.0000x reference)
#include <cuda_runtime.h>
#include <math.h>

#define NBATCH 64
#define NCAT   128
#define NK     127
#define NTYPE  6
#define NCH    36

#define W2_RP  28   // padded row length for 25-wide W2 rows
#define W3_RP  52   // padded row length for 50-wide W3 rows
#define OUT_ST 101  // smem row stride for out (coprime with 32 -> conflict-free)

// padded weights + per-center sorted neighbor lists (scratch: __device__ globals, no allocs)
__device__ float g_W2p[NCH * 50 * W2_RP];
__device__ float g_W3p[NCH * 100 * W3_RP];
__device__ int   g_srtj[NCAT * NK];
__device__ int   g_srtch[NCAT * NK];

__device__ __forceinline__ float tanh_fast(float v) {
    float av = fabsf(v);
    float e  = __expf(-2.0f * av);
    float r  = __fdividef(1.0f - e, 1.0f + e);
    return copysignf(r, v);
}

__global__ void prep_weights(const float* __restrict__ W2, const float* __restrict__ W3) {
    const int n2 = NCH * 50 * W2_RP;
    const int n3 = NCH * 100 * W3_RP;
    for (int i = blockIdx.x * blockDim.x + threadIdx.x; i < n2 + n3;
         i += gridDim.x * blockDim.x) {
        if (i < n2) {
            int col = i % W2_RP, row = i / W2_RP;
            g_W2p[i] = (col < 25) ? W2[row * 25 + col] : 0.0f;
        } else {
            int ii = i - n2;
            int col = ii % W3_RP, row = ii / W3_RP;
            g_W3p[ii] = (col < 50) ? W3[row * 50 + col] : 0.0f;
        }
    }
}

// counting-sort each center's 127 neighbors by neighbor type so warps in the
// main kernel see (mostly) uniform channels -> broadcast weight loads.
__global__ void prep_sort(const int* __restrict__ types) {
    __shared__ int ts[NCAT];
    int t = threadIdx.x;
    if (t < NCAT) ts[t] = types[t];
    __syncthreads();
    if (t >= NCAT) return;
    const int n  = t;
    const int tn = ts[n];
    int cnt[NTYPE];
#pragma unroll
    for (int i = 0; i < NTYPE; i++) cnt[i] = 0;
    for (int kk = 0; kk < NK; kk++) {
        int j = kk + (kk >= n ? 1 : 0);
        cnt[ts[j]]++;
    }
    int off[NTYPE];
    int ssum = 0;
#pragma unroll
    for (int i = 0; i < NTYPE; i++) { off[i] = ssum; ssum += cnt[i]; }
    for (int kk = 0; kk < NK; kk++) {
        int j  = kk + (kk >= n ? 1 : 0);
        int ty = ts[j];
        int pos = off[ty]++;
        g_srtj[n * NK + pos]  = j;
        g_srtch[n * NK + pos] = tn * NTYPE + ty;
    }
}

// One block per (b, n); thread k = one (sorted) neighbor pair.
__global__ __launch_bounds__(128)
void feature_main(const float* __restrict__ coords,
                  const float* __restrict__ W1, const float* __restrict__ b1,
                  const float* __restrict__ b2, const float* __restrict__ b3,
                  float* __restrict__ outp) {
    extern __shared__ float sm[];
    float* cs    = sm;                      // 384 : coords of this batch
    float* a_s   = sm + 384;                // 384 : loc_env_a per k
    float* out_s = sm + 768;                // 127*101 -> 12832 (padded)
    float* t2_s  = sm + 768 + 12832;        // 512
    float* t1_s  = t2_s + 512;              // 16
    float* red   = t1_s + 16;               // 48

    const int n   = blockIdx.x;
    const int b   = blockIdx.y;
    const int tid = threadIdx.x;

    for (int i = tid; i < NCAT * 3; i += 128)
        cs[i] = coords[(size_t)b * NCAT * 3 + i];
    __syncthreads();

    float p[12];
#pragma unroll
    for (int i = 0; i < 12; i++) p[i] = 0.0f;

    float ax = 0.0f, ay = 0.0f, az = 0.0f;
    const int k = tid;

    if (k < NK) {
        const int j  = g_srtj[n * NK + k];
        const int ch = g_srtch[n * NK + k];

        float rx = cs[n * 3 + 0] - cs[j * 3 + 0];
        float ry = cs[n * 3 + 1] - cs[j * 3 + 1];
        float rz = cs[n * 3 + 2] - cs[j * 3 + 2];
        float d2 = rx * rx + ry * ry + rz * rz;
        float d  = sqrtf(d2);
        float dinv = 1.0f / fmaxf(d, 1e-12f);
        float x = dinv;
        float s = dinv * dinv;
        ax = rx * s; ay = ry * s; az = rz * s;
        a_s[k * 3 + 0] = ax;
        a_s[k * 3 + 1] = ay;
        a_s[k * 3 + 2] = az;

        // ---- layer 1: 1 -> 25 ----
        float y1[W2_RP];
        {
            const float* w1 = W1 + ch * 25;
            const float* bb = b1 + ch * 25;
#pragma unroll
            for (int o = 0; o < 25; o++)
                y1[o] = tanh_fast(fmaf(w1[o], x, bb[o]));
            y1[25] = y1[26] = y1[27] = 0.0f;
        }

        // ---- layer 2: 25 -> 50, residual concat([y1,y1]) ----
        float y2[W3_RP];
        {
            const float4* w2 = (const float4*)(g_W2p + ch * 50 * W2_RP);
            const float*  bb = b2 + ch * 50;
#pragma unroll
            for (int o = 0; o < 50; o++) {
                float acc = bb[o];
                const float4* row = w2 + o * (W2_RP / 4);
#pragma unroll
                for (int q = 0; q < W2_RP / 4; q++) {
                    float4 w = row[q];
                    acc = fmaf(w.x, y1[4 * q + 0], acc);
                    acc = fmaf(w.y, y1[4 * q + 1], acc);
                    acc = fmaf(w.z, y1[4 * q + 2], acc);
                    acc = fmaf(w.w, y1[4 * q + 3], acc);
                }
                y2[o] = tanh_fast(acc) + y1[(o < 25) ? o : (o - 25)];
            }
            y2[50] = y2[51] = 0.0f;
        }

        // ---- layer 3: 50 -> 100, residual concat([y2,y2]) ----
        {
            const float4* w3 = (const float4*)(g_W3p + ch * 100 * W3_RP);
            const float*  bb = b3 + ch * 100;
#pragma unroll
            for (int o = 0; o < 100; o++) {
                float acc = bb[o];
                const float4* row = w3 + o * (W3_RP / 4);
#pragma unroll
                for (int q = 0; q < W3_RP / 4; q++) {
                    float4 w = row[q];
                    acc = fmaf(w.x, y2[4 * q + 0], acc);
                    acc = fmaf(w.y, y2[4 * q + 1], acc);
                    acc = fmaf(w.z, y2[4 * q + 2], acc);
                    acc = fmaf(w.w, y2[4 * q + 3], acc);
                }
                float v = tanh_fast(acc) + y2[(o < 50) ? o : (o - 50)];
                out_s[k * OUT_ST + o] = v;
                if (o < 4) {  // t1 partial with first-4 features kept in regs
                    p[0 + o] = ax * v;
                    p[4 + o] = ay * v;
                    p[8 + o] = az * v;
                }
            }
        }
    }

    // ---- t1[a][f] = sum_k a[k][a] * out[k][f<4] : block reduction ----
#pragma unroll
    for (int i = 0; i < 12; i++) {
#pragma unroll
        for (int sh = 16; sh > 0; sh >>= 1)
            p[i] += __shfl_xor_sync(0xffffffffu, p[i], sh);
    }
    const int warp = tid >> 5, lane = tid & 31;
    if (lane == 0) {
#pragma unroll
        for (int i = 0; i < 12; i++) red[warp * 12 + i] = p[i];
    }
    __syncthreads();
    if (tid < 12)
        t1_s[tid] = red[tid] + red[12 + tid] + red[24 + tid] + red[36 + tid];
    __syncthreads();

    // ---- t2[k][f] = sum_a a[k][a] * t1[a][f] ----
    if (k < NK) {
        float4 t2;
        t2.x = ax * t1_s[0] + ay * t1_s[4] + az * t1_s[8];
        t2.y = ax * t1_s[1] + ay * t1_s[5] + az * t1_s[9];
        t2.z = ax * t1_s[2] + ay * t1_s[6] + az * t1_s[10];
        t2.w = ax * t1_s[3] + ay * t1_s[7] + az * t1_s[11];
        *(float4*)(t2_s + k * 4) = t2;
    }
    __syncthreads();

    // ---- res[g][f] = sum_k out[k][g] * t2[k][f] ----
    if (tid < 100) {
        const int g = tid;
        float a0 = 0.0f, a1 = 0.0f, a2 = 0.0f, a3 = 0.0f;
#pragma unroll 4
        for (int kk = 0; kk < NK; kk++) {
            float  og = out_s[kk * OUT_ST + g];
            float4 t  = *(const float4*)(t2_s + kk * 4);
            a0 = fmaf(og, t.x, a0);
            a1 = fmaf(og, t.y, a1);
            a2 = fmaf(og, t.z, a2);
            a3 = fmaf(og, t.w, a3);
        }
        float4 r;
        r.x = a0; r.y = a1; r.z = a2; r.w = a3;
        *(float4*)(outp + ((size_t)(b * NCAT + n)) * 400 + g * 4) = r;
    }
}

extern "C" void kernel_launch(void* const* d_in, const int* in_sizes, int n_in,
                              void* d_out, int out_size) {
    const float* coords     = (const float*)d_in[0];
    const int*   atom_types = (const int*)d_in[1];
    const float* W1 = (const float*)d_in[2];
    const float* b1 = (const float*)d_in[3];
    const float* W2 = (const float*)d_in[4];
    const float* b2 = (const float*)d_in[5];
    const float* W3 = (const float*)d_in[6];
    const float* b3 = (const float*)d_in[7];
    float* outp = (float*)d_out;

    prep_weights<<<256, 256>>>(W2, W3);
    prep_sort<<<1, 128>>>(atom_types);

    const size_t smem_bytes = (384 + 384 + 12832 + 512 + 16 + 48) * sizeof(float); // 56704
    cudaFuncSetAttribute(feature_main, cudaFuncAttributeMaxDynamicSharedMemorySize,
                         (int)smem_bytes);
    feature_main<<<dim3(NCAT, NBATCH), 128, smem_bytes>>>(coords, W1, b1, b2, b3, outp);
}

// round 5
// speedup vs baseline: 1.5935x; 1.5935x over previous
#include <cuda_runtime.h>
#include <math.h>

#define NBATCH 64
#define NCAT   128
#define NK     127
#define NTYPE  6
#define NCH    36
#define NUNIT  (NCAT * NK)       // 16256 (n,j) units
#define NSLOT  (NUNIT * 2)       // 32512 warp-slots (2 batch halves per unit)
#define NPLAN  (NSLOT + NCH * 4) // padded plan capacity
#define NBLK1  (NPLAN / 4)       // K1 blocks (4 warp-slots each)

// per-channel packed weight block layout (floats):
// [0,25)=W1  [25,50)=b1  [50,100)=b2  [100,200)=b3
// [200,1600)=W2 rows padded to 28   [1600,6800)=W3 rows padded to 52
#define CHW 6800

__device__ float g_Wall[NCH * CHW];
__device__ int   g_plan[NPLAN];
__device__ float g_out[(size_t)NBATCH * NCAT * NK * 100];  // MLP outputs

// ---------------- f32x2 helpers ----------------
__device__ __forceinline__ unsigned long long pk2(float lo, float hi) {
    unsigned long long r;
    asm("mov.b64 %0, {%1, %2};" : "=l"(r) : "f"(lo), "f"(hi));
    return r;
}
__device__ __forceinline__ void unp2(unsigned long long v, float& lo, float& hi) {
    asm("mov.b64 {%0, %1}, %2;" : "=f"(lo), "=f"(hi) : "l"(v));
}
__device__ __forceinline__ unsigned long long fma2w(float wlo, float whi,
                                                    unsigned long long x,
                                                    unsigned long long acc) {
    unsigned long long w = pk2(wlo, whi);
    unsigned long long r;
    asm("fma.rn.f32x2 %0, %1, %2, %3;" : "=l"(r) : "l"(w), "l"(x), "l"(acc));
    return r;
}
// accurate tanh (proved rel_err 3e-7 in the R2 passing kernel)
__device__ __forceinline__ float tanh_acc(float v) {
    float av = fabsf(v);
    float e  = __expf(-2.0f * av);
    float r  = __fdividef(1.0f - e, 1.0f + e);
    return copysignf(r, v);
}

// ---------------- prep: pack per-channel weight blocks ----------------
__global__ void prep_pack(const float* __restrict__ W1, const float* __restrict__ b1,
                          const float* __restrict__ W2, const float* __restrict__ b2,
                          const float* __restrict__ W3, const float* __restrict__ b3) {
    int i = blockIdx.x * blockDim.x + threadIdx.x;
    if (i >= NCH * CHW) return;
    int ch = i / CHW;
    int r  = i % CHW;
    float v;
    if (r < 25)        v = W1[ch * 25 + r];
    else if (r < 50)   v = b1[ch * 25 + (r - 25)];
    else if (r < 100)  v = b2[ch * 50 + (r - 50)];
    else if (r < 200)  v = b3[ch * 100 + (r - 100)];
    else if (r < 1600) {
        int rr = r - 200, o = rr / 28, c = rr % 28;
        v = (c < 25) ? W2[(ch * 50 + o) * 25 + c] : 0.0f;
    } else {
        int rr = r - 1600, o = rr / 52, c = rr % 52;
        v = (c < 50) ? W3[(ch * 100 + o) * 50 + c] : 0.0f;
    }
    g_Wall[i] = v;
}

// ---------------- prep: channel-pure warp-slot plan ----------------
__global__ void prep_plan(const int* __restrict__ types) {
    __shared__ int ts[NCAT];
    __shared__ int cnt[NCH];
    __shared__ int off[NCH];
    int t = threadIdx.x;

    for (int i = t; i < NPLAN; i += 256) g_plan[i] = -1;
    if (t < NCAT) ts[t] = types[t];
    if (t < NCH)  cnt[t] = 0;
    __syncthreads();

    for (int u = t; u < NUNIT; u += 256) {
        int n = u / NK, k = u % NK;
        int j = k + (k >= n ? 1 : 0);
        atomicAdd(&cnt[ts[n] * NTYPE + ts[j]], 2);
    }
    __syncthreads();
    if (t == 0) {
        int run = 0;
        for (int c = 0; c < NCH; c++) {
            off[c] = run;
            run += (cnt[c] + 3) & ~3;   // pad each channel to a multiple of 4 slots
        }
    }
    __syncthreads();
    for (int u = t; u < NUNIT; u += 256) {
        int n = u / NK, k = u % NK;
        int j = k + (k >= n ? 1 : 0);
        int c = ts[n] * NTYPE + ts[j];
        int pos = atomicAdd(&off[c], 2);
        g_plan[pos]     = u * 2;
        g_plan[pos + 1] = u * 2 + 1;
    }
}

// ---------------- K1: per-pair MLP, f32x2 split-accumulator ----------------
__global__ __launch_bounds__(128)
void k1_mlp(const float* __restrict__ coords, const int* __restrict__ types) {
    __shared__ __align__(16) float sw[CHW];

    const int tid  = threadIdx.x;
    const int wid  = tid >> 5;
    const int lane = tid & 31;

    int slot0 = g_plan[blockIdx.x * 4];
    if (slot0 < 0) return;                 // fully-padding block (uniform exit)

    // block channel from first slot (blocks are channel-pure by construction)
    {
        int u0 = slot0 >> 1;
        int n0 = u0 / NK, k0 = u0 % NK;
        int j0 = k0 + (k0 >= n0 ? 1 : 0);
        int ch = types[n0] * NTYPE + types[j0];
        const float4* src = (const float4*)(g_Wall + ch * CHW);
        float4* dst = (float4*)sw;
        for (int i = tid; i < CHW / 4; i += 128) dst[i] = src[i];
    }
    __syncthreads();

    int slot = g_plan[blockIdx.x * 4 + wid];
    if (slot < 0) return;                  // padding warp (after the only sync)

    const int u = slot >> 1;
    const int n = u / NK;
    const int k = u % NK;
    const int j = k + (k >= n ? 1 : 0);
    const int b = lane + ((slot & 1) << 5);

    const float* cb = coords + (size_t)b * NCAT * 3;
    float rx = cb[n * 3 + 0] - cb[j * 3 + 0];
    float ry = cb[n * 3 + 1] - cb[j * 3 + 1];
    float rz = cb[n * 3 + 2] - cb[j * 3 + 2];
    float d  = sqrtf(rx * rx + ry * ry + rz * rz);
    float x  = 1.0f / fmaxf(d, 1e-12f);

    // ---- layer 1: 1 -> 25 ----
    float y1[25];
#pragma unroll
    for (int o = 0; o < 25; o++)
        y1[o] = tanh_acc(fmaf(sw[o], x, sw[25 + o]));

    unsigned long long y1p[14];
#pragma unroll
    for (int q = 0; q < 12; q++) y1p[q] = pk2(y1[2 * q], y1[2 * q + 1]);
    y1p[12] = pk2(y1[24], 0.0f);
    y1p[13] = pk2(0.0f, 0.0f);

    // ---- layer 2: 25 -> 50 (+ concat residual) ----
    unsigned long long y2p[26];
#pragma unroll
    for (int o = 0; o < 50; o += 2) {
        const float4* r0 = (const float4*)(sw + 200 + o * 28);
        const float4* r1 = (const float4*)(sw + 200 + (o + 1) * 28);
        unsigned long long a0 = pk2(0.0f, 0.0f), a1 = pk2(0.0f, 0.0f);
#pragma unroll
        for (int q = 0; q < 7; q++) {
            float4 w0 = r0[q], w1 = r1[q];
            a0 = fma2w(w0.x, w0.y, y1p[2 * q], a0);
            a0 = fma2w(w0.z, w0.w, y1p[2 * q + 1], a0);
            a1 = fma2w(w1.x, w1.y, y1p[2 * q], a1);
            a1 = fma2w(w1.z, w1.w, y1p[2 * q + 1], a1);
        }
        float l0, h0, l1, h1;
        unp2(a0, l0, h0);
        unp2(a1, l1, h1);
        int i0 = (o < 25) ? o : o - 25;
        int i1 = (o + 1 < 25) ? o + 1 : o - 24;
        float v0 = tanh_acc(l0 + h0 + sw[50 + o])     + y1[i0];
        float v1 = tanh_acc(l1 + h1 + sw[50 + o + 1]) + y1[i1];
        y2p[o / 2] = pk2(v0, v1);
    }
    y2p[25] = pk2(0.0f, 0.0f);

    // ---- layer 3: 50 -> 100 (+ concat residual), write to g_out ----
    float* op = g_out + (((size_t)b * NCAT + n) * NK + k) * 100;
#pragma unroll
    for (int o = 0; o < 100; o += 4) {
        const float4* r0 = (const float4*)(sw + 1600 + (o + 0) * 52);
        const float4* r1 = (const float4*)(sw + 1600 + (o + 1) * 52);
        const float4* r2 = (const float4*)(sw + 1600 + (o + 2) * 52);
        const float4* r3 = (const float4*)(sw + 1600 + (o + 3) * 52);
        unsigned long long a0 = pk2(0.0f, 0.0f), a1 = a0, a2 = a0, a3 = a0;
#pragma unroll
        for (int q = 0; q < 13; q++) {
            unsigned long long xa = y2p[2 * q], xb = y2p[2 * q + 1];
            float4 w0 = r0[q];
            a0 = fma2w(w0.x, w0.y, xa, a0);
            a0 = fma2w(w0.z, w0.w, xb, a0);
            float4 w1 = r1[q];
            a1 = fma2w(w1.x, w1.y, xa, a1);
            a1 = fma2w(w1.z, w1.w, xb, a1);
            float4 w2 = r2[q];
            a2 = fma2w(w2.x, w2.y, xa, a2);
            a2 = fma2w(w2.z, w2.w, xb, a2);
            float4 w3 = r3[q];
            a3 = fma2w(w3.x, w3.y, xa, a3);
            a3 = fma2w(w3.z, w3.w, xb, a3);
        }
        float4 res;
        float lo, hi, rl, rh;

        // residual index computed PER ELEMENT (R3 bug: was per group of 4)
        {
            int ib = ((o + 0) < 50) ? (o + 0) : (o + 0 - 50);
            unp2(a0, lo, hi);
            unp2(y2p[ib >> 1], rl, rh);
            res.x = tanh_acc(lo + hi + sw[100 + o + 0]) + ((ib & 1) ? rh : rl);
        }
        {
            int ib = ((o + 1) < 50) ? (o + 1) : (o + 1 - 50);
            unp2(a1, lo, hi);
            unp2(y2p[ib >> 1], rl, rh);
            res.y = tanh_acc(lo + hi + sw[100 + o + 1]) + ((ib & 1) ? rh : rl);
        }
        {
            int ib = ((o + 2) < 50) ? (o + 2) : (o + 2 - 50);
            unp2(a2, lo, hi);
            unp2(y2p[ib >> 1], rl, rh);
            res.z = tanh_acc(lo + hi + sw[100 + o + 2]) + ((ib & 1) ? rh : rl);
        }
        {
            int ib = ((o + 3) < 50) ? (o + 3) : (o + 3 - 50);
            unp2(a3, lo, hi);
            unp2(y2p[ib >> 1], rl, rh);
            res.w = tanh_acc(lo + hi + sw[100 + o + 3]) + ((ib & 1) ? rh : rl);
        }

        *(float4*)(op + o) = res;
    }
}

// ---------------- K2: contractions per (b, n) ----------------
__global__ __launch_bounds__(128)
void k2_contract(const float* __restrict__ coords, float* __restrict__ outp) {
    __shared__ float cs[NCAT * 3];
    __shared__ float t2s[NK * 4];
    __shared__ float t1s[12];
    __shared__ float red[48];

    const int n   = blockIdx.x;
    const int b   = blockIdx.y;
    const int tid = threadIdx.x;

    for (int i = tid; i < NCAT * 3; i += 128)
        cs[i] = coords[(size_t)b * NCAT * 3 + i];
    __syncthreads();

    const float* obase = g_out + (((size_t)b * NCAT + n) * NK) * 100;

    float p[12];
#pragma unroll
    for (int i = 0; i < 12; i++) p[i] = 0.0f;
    float ax = 0.0f, ay = 0.0f, az = 0.0f;
    const int k = tid;

    if (k < NK) {
        int j = k + (k >= n ? 1 : 0);
        float rx = cs[n * 3 + 0] - cs[j * 3 + 0];
        float ry = cs[n * 3 + 1] - cs[j * 3 + 1];
        float rz = cs[n * 3 + 2] - cs[j * 3 + 2];
        float d  = sqrtf(rx * rx + ry * ry + rz * rz);
        float dinv = 1.0f / fmaxf(d, 1e-12f);
        float s = dinv * dinv;
        ax = rx * s; ay = ry * s; az = rz * s;

        float4 o4 = *(const float4*)(obase + (size_t)k * 100);
        p[0] = ax * o4.x; p[1] = ax * o4.y; p[2]  = ax * o4.z; p[3]  = ax * o4.w;
        p[4] = ay * o4.x; p[5] = ay * o4.y; p[6]  = ay * o4.z; p[7]  = ay * o4.w;
        p[8] = az * o4.x; p[9] = az * o4.y; p[10] = az * o4.z; p[11] = az * o4.w;
    }

#pragma unroll
    for (int i = 0; i < 12; i++) {
#pragma unroll
        for (int sh = 16; sh > 0; sh >>= 1)
            p[i] += __shfl_xor_sync(0xffffffffu, p[i], sh);
    }
    const int warp = tid >> 5, lane = tid & 31;
    if (lane == 0) {
#pragma unroll
        for (int i = 0; i < 12; i++) red[warp * 12 + i] = p[i];
    }
    __syncthreads();
    if (tid < 12)
        t1s[tid] = red[tid] + red[12 + tid] + red[24 + tid] + red[36 + tid];
    __syncthreads();

    if (k < NK) {
        float4 t2;
        t2.x = ax * t1s[0] + ay * t1s[4] + az * t1s[8];
        t2.y = ax * t1s[1] + ay * t1s[5] + az * t1s[9];
        t2.z = ax * t1s[2] + ay * t1s[6] + az * t1s[10];
        t2.w = ax * t1s[3] + ay * t1s[7] + az * t1s[11];
        *(float4*)(t2s + k * 4) = t2;
    }
    __syncthreads();

    if (tid < 100) {
        const int g = tid;
        float a0 = 0.0f, a1 = 0.0f, a2 = 0.0f, a3 = 0.0f;
#pragma unroll 4
        for (int kk = 0; kk < NK; kk++) {
            float  og = obase[(size_t)kk * 100 + g];
            float4 t  = *(const float4*)(t2s + kk * 4);
            a0 = fmaf(og, t.x, a0);
            a1 = fmaf(og, t.y, a1);
            a2 = fmaf(og, t.z, a2);
            a3 = fmaf(og, t.w, a3);
        }
        float4 r; r.x = a0; r.y = a1; r.z = a2; r.w = a3;
        *(float4*)(outp + ((size_t)(b * NCAT + n)) * 400 + g * 4) = r;
    }
}

extern "C" void kernel_launch(void* const* d_in, const int* in_sizes, int n_in,
                              void* d_out, int out_size) {
    const float* coords     = (const float*)d_in[0];
    const int*   atom_types = (const int*)d_in[1];
    const float* W1 = (const float*)d_in[2];
    const float* b1 = (const float*)d_in[3];
    const float* W2 = (const float*)d_in[4];
    const float* b2 = (const float*)d_in[5];
    const float* W3 = (const float*)d_in[6];
    const float* b3 = (const float*)d_in[7];
    float* outp = (float*)d_out;

    prep_pack<<<(NCH * CHW + 255) / 256, 256>>>(W1, b1, W2, b2, W3, b3);
    prep_plan<<<1, 256>>>(atom_types);
    k1_mlp<<<NBLK1, 128>>>(coords, atom_types);
    k2_contract<<<dim3(NCAT, NBATCH), 128>>>(coords, outp);
}

// round 6
// speedup vs baseline: 1.8573x; 1.1656x over previous
#include <cuda_runtime.h>
#include <cuda_fp16.h>
#include <math.h>

#define NBATCH 64
#define NCAT   128
#define NK     127
#define NTYPE  6
#define NCH    36
#define NUNIT  (NCAT * NK)       // 16256 (n,j) units
#define NSLOT  (NUNIT * 2)       // 32512 warp-slots (2 batch halves per unit)
#define NPLAN  (NSLOT + NCH * 4) // padded plan capacity
#define NBLK1  (NPLAN / 4)       // K1 blocks (4 warp-slots each)

// per-channel packed weight block layout (floats):
// [0,25)=W1  [25,50)=b1  [50,100)=b2  [100,200)=b3
// [200,1600)=W2 rows padded to 28   [1600,6800)=W3 rows padded to 52
#define CHW 6800

__device__ float  g_Wall[NCH * CHW];
__device__ int    g_plan[NPLAN];
__device__ __half g_out[(size_t)NBATCH * NCAT * NK * 100];  // MLP outputs (fp16)

// ---------------- f32x2 helpers ----------------
__device__ __forceinline__ unsigned long long pk2(float lo, float hi) {
    unsigned long long r;
    asm("mov.b64 %0, {%1, %2};" : "=l"(r) : "f"(lo), "f"(hi));
    return r;
}
__device__ __forceinline__ void unp2(unsigned long long v, float& lo, float& hi) {
    asm("mov.b64 {%0, %1}, %2;" : "=f"(lo), "=f"(hi) : "l"(v));
}
__device__ __forceinline__ unsigned long long fma2w(float wlo, float whi,
                                                    unsigned long long x,
                                                    unsigned long long acc) {
    unsigned long long w = pk2(wlo, whi);
    unsigned long long r;
    asm("fma.rn.f32x2 %0, %1, %2, %3;" : "=l"(r) : "l"(w), "l"(x), "l"(acc));
    return r;
}
// 5-op accurate tanh: 1 - 2*rcp(2^(2*log2e*v) + 1); exact at both limits.
__device__ __forceinline__ float tanh5(float v) {
    float e;
    asm("ex2.approx.ftz.f32 %0, %1;" : "=f"(e) : "f"(v * 2.885390082f));
    float r;
    asm("rcp.approx.ftz.f32 %0, %1;" : "=f"(r) : "f"(e + 1.0f));
    return fmaf(-2.0f, r, 1.0f);
}

// ---------------- prep: pack per-channel weight blocks ----------------
__global__ void prep_pack(const float* __restrict__ W1, const float* __restrict__ b1,
                          const float* __restrict__ W2, const float* __restrict__ b2,
                          const float* __restrict__ W3, const float* __restrict__ b3) {
    int i = blockIdx.x * blockDim.x + threadIdx.x;
    if (i >= NCH * CHW) return;
    int ch = i / CHW;
    int r  = i % CHW;
    float v;
    if (r < 25)        v = W1[ch * 25 + r];
    else if (r < 50)   v = b1[ch * 25 + (r - 25)];
    else if (r < 100)  v = b2[ch * 50 + (r - 50)];
    else if (r < 200)  v = b3[ch * 100 + (r - 100)];
    else if (r < 1600) {
        int rr = r - 200, o = rr / 28, c = rr % 28;
        v = (c < 25) ? W2[(ch * 50 + o) * 25 + c] : 0.0f;
    } else {
        int rr = r - 1600, o = rr / 52, c = rr % 52;
        v = (c < 50) ? W3[(ch * 100 + o) * 50 + c] : 0.0f;
    }
    g_Wall[i] = v;
}

// ---------------- prep: channel-pure warp-slot plan ----------------
__global__ void prep_plan(const int* __restrict__ types) {
    __shared__ int ts[NCAT];
    __shared__ int cnt[NCH];
    __shared__ int off[NCH];
    int t = threadIdx.x;

    for (int i = t; i < NPLAN; i += 256) g_plan[i] = -1;
    if (t < NCAT) ts[t] = types[t];
    if (t < NCH)  cnt[t] = 0;
    __syncthreads();

    for (int u = t; u < NUNIT; u += 256) {
        int n = u / NK, k = u % NK;
        int j = k + (k >= n ? 1 : 0);
        atomicAdd(&cnt[ts[n] * NTYPE + ts[j]], 2);
    }
    __syncthreads();
    if (t == 0) {
        int run = 0;
        for (int c = 0; c < NCH; c++) {
            off[c] = run;
            run += (cnt[c] + 3) & ~3;   // pad each channel to a multiple of 4 slots
        }
    }
    __syncthreads();
    for (int u = t; u < NUNIT; u += 256) {
        int n = u / NK, k = u % NK;
        int j = k + (k >= n ? 1 : 0);
        int c = ts[n] * NTYPE + ts[j];
        int pos = atomicAdd(&off[c], 2);
        g_plan[pos]     = u * 2;
        g_plan[pos + 1] = u * 2 + 1;
    }
}

// ---------------- K1: per-pair MLP, f32x2 split-accumulator ----------------
__global__ __launch_bounds__(128, 4)
void k1_mlp(const float* __restrict__ coords, const int* __restrict__ types) {
    __shared__ __align__(16) float sw[CHW];

    const int tid  = threadIdx.x;
    const int wid  = tid >> 5;
    const int lane = tid & 31;

    int slot0 = g_plan[blockIdx.x * 4];
    if (slot0 < 0) return;                 // fully-padding block (uniform exit)

    // block channel from first slot (blocks are channel-pure by construction)
    {
        int u0 = slot0 >> 1;
        int n0 = u0 / NK, k0 = u0 % NK;
        int j0 = k0 + (k0 >= n0 ? 1 : 0);
        int ch = types[n0] * NTYPE + types[j0];
        const float4* src = (const float4*)(g_Wall + ch * CHW);
        float4* dst = (float4*)sw;
        for (int i = tid; i < CHW / 4; i += 128) dst[i] = src[i];
    }
    __syncthreads();

    int slot = g_plan[blockIdx.x * 4 + wid];
    if (slot < 0) return;                  // padding warp (after the only sync)

    const int u = slot >> 1;
    const int n = u / NK;
    const int k = u % NK;
    const int j = k + (k >= n ? 1 : 0);
    const int b = lane + ((slot & 1) << 5);

    const float* cb = coords + (size_t)b * NCAT * 3;
    float rx = cb[n * 3 + 0] - cb[j * 3 + 0];
    float ry = cb[n * 3 + 1] - cb[j * 3 + 1];
    float rz = cb[n * 3 + 2] - cb[j * 3 + 2];
    float d  = sqrtf(rx * rx + ry * ry + rz * rz);
    float x  = 1.0f / fmaxf(d, 1e-12f);

    // ---- layer 1: 1 -> 25, produced directly as f32x2 pairs ----
    unsigned long long y1p[14];
#pragma unroll
    for (int q = 0; q < 12; q++) {
        float v0 = tanh5(fmaf(sw[2 * q],     x, sw[25 + 2 * q]));
        float v1 = tanh5(fmaf(sw[2 * q + 1], x, sw[25 + 2 * q + 1]));
        y1p[q] = pk2(v0, v1);
    }
    y1p[12] = pk2(tanh5(fmaf(sw[24], x, sw[49])), 0.0f);
    y1p[13] = pk2(0.0f, 0.0f);

    // ---- layer 2: 25 -> 50 (+ concat residual) ----
    unsigned long long y2p[26];
#pragma unroll
    for (int o = 0; o < 50; o += 2) {
        const float4* r0 = (const float4*)(sw + 200 + o * 28);
        const float4* r1 = (const float4*)(sw + 200 + (o + 1) * 28);
        unsigned long long a0 = pk2(0.0f, 0.0f), a1 = pk2(0.0f, 0.0f);
#pragma unroll
        for (int q = 0; q < 7; q++) {
            float4 w0 = r0[q], w1 = r1[q];
            a0 = fma2w(w0.x, w0.y, y1p[2 * q], a0);
            a0 = fma2w(w0.z, w0.w, y1p[2 * q + 1], a0);
            a1 = fma2w(w1.x, w1.y, y1p[2 * q], a1);
            a1 = fma2w(w1.z, w1.w, y1p[2 * q + 1], a1);
        }
        float l0, h0, l1, h1, rl, rh;
        unp2(a0, l0, h0);
        unp2(a1, l1, h1);
        // residual from y1p halves (compile-time indices)
        int i0 = (o < 25) ? o : o - 25;
        int i1 = (o + 1 < 25) ? o + 1 : o - 24;
        float res0, res1;
        unp2(y1p[i0 >> 1], rl, rh);
        res0 = (i0 & 1) ? rh : rl;
        unp2(y1p[i1 >> 1], rl, rh);
        res1 = (i1 & 1) ? rh : rl;
        float v0 = tanh5(l0 + h0 + sw[50 + o])     + res0;
        float v1 = tanh5(l1 + h1 + sw[50 + o + 1]) + res1;
        y2p[o / 2] = pk2(v0, v1);
    }
    y2p[25] = pk2(0.0f, 0.0f);

    // ---- layer 3: 50 -> 100 (+ concat residual), write fp16 to g_out ----
    __half* op = g_out + (((size_t)b * NCAT + n) * NK + k) * 100;
#pragma unroll
    for (int o = 0; o < 100; o += 4) {
        const float4* r0 = (const float4*)(sw + 1600 + (o + 0) * 52);
        const float4* r1 = (const float4*)(sw + 1600 + (o + 1) * 52);
        const float4* r2 = (const float4*)(sw + 1600 + (o + 2) * 52);
        const float4* r3 = (const float4*)(sw + 1600 + (o + 3) * 52);
        unsigned long long a0 = pk2(0.0f, 0.0f), a1 = a0, a2 = a0, a3 = a0;
#pragma unroll
        for (int q = 0; q < 13; q++) {
            unsigned long long xa = y2p[2 * q], xb = y2p[2 * q + 1];
            float4 w0 = r0[q];
            a0 = fma2w(w0.x, w0.y, xa, a0);
            a0 = fma2w(w0.z, w0.w, xb, a0);
            float4 w1 = r1[q];
            a1 = fma2w(w1.x, w1.y, xa, a1);
            a1 = fma2w(w1.z, w1.w, xb, a1);
            float4 w2 = r2[q];
            a2 = fma2w(w2.x, w2.y, xa, a2);
            a2 = fma2w(w2.z, w2.w, xb, a2);
            float4 w3 = r3[q];
            a3 = fma2w(w3.x, w3.y, xa, a3);
            a3 = fma2w(w3.z, w3.w, xb, a3);
        }
        float vx, vy, vz, vw;
        float lo, hi, rl, rh;
        {
            int ib = ((o + 0) < 50) ? (o + 0) : (o + 0 - 50);
            unp2(a0, lo, hi);
            unp2(y2p[ib >> 1], rl, rh);
            vx = tanh5(lo + hi + sw[100 + o + 0]) + ((ib & 1) ? rh : rl);
        }
        {
            int ib = ((o + 1) < 50) ? (o + 1) : (o + 1 - 50);
            unp2(a1, lo, hi);
            unp2(y2p[ib >> 1], rl, rh);
            vy = tanh5(lo + hi + sw[100 + o + 1]) + ((ib & 1) ? rh : rl);
        }
        {
            int ib = ((o + 2) < 50) ? (o + 2) : (o + 2 - 50);
            unp2(a2, lo, hi);
            unp2(y2p[ib >> 1], rl, rh);
            vz = tanh5(lo + hi + sw[100 + o + 2]) + ((ib & 1) ? rh : rl);
        }
        {
            int ib = ((o + 3) < 50) ? (o + 3) : (o + 3 - 50);
            unp2(a3, lo, hi);
            unp2(y2p[ib >> 1], rl, rh);
            vw = tanh5(lo + hi + sw[100 + o + 3]) + ((ib & 1) ? rh : rl);
        }
        __half2 h0 = __floats2half2_rn(vx, vy);
        __half2 h1 = __floats2half2_rn(vz, vw);
        uint2 st;
        st.x = *(unsigned int*)&h0;
        st.y = *(unsigned int*)&h1;
        *(uint2*)(op + o) = st;   // 8B aligned: rows are 200B, o%4==0
    }
}

// ---------------- K2: contractions per (b, n) ----------------
__global__ __launch_bounds__(128)
void k2_contract(const float* __restrict__ coords, float* __restrict__ outp) {
    __shared__ float cs[NCAT * 3];
    __shared__ float t2s[NK * 4];
    __shared__ float t1s[12];
    __shared__ float red[48];

    const int n   = blockIdx.x;
    const int b   = blockIdx.y;
    const int tid = threadIdx.x;

    for (int i = tid; i < NCAT * 3; i += 128)
        cs[i] = coords[(size_t)b * NCAT * 3 + i];
    __syncthreads();

    const __half* obase = g_out + (((size_t)b * NCAT + n) * NK) * 100;

    float p[12];
#pragma unroll
    for (int i = 0; i < 12; i++) p[i] = 0.0f;
    float ax = 0.0f, ay = 0.0f, az = 0.0f;
    const int k = tid;

    if (k < NK) {
        int j = k + (k >= n ? 1 : 0);
        float rx = cs[n * 3 + 0] - cs[j * 3 + 0];
        float ry = cs[n * 3 + 1] - cs[j * 3 + 1];
        float rz = cs[n * 3 + 2] - cs[j * 3 + 2];
        float d  = sqrtf(rx * rx + ry * ry + rz * rz);
        float dinv = 1.0f / fmaxf(d, 1e-12f);
        float s = dinv * dinv;
        ax = rx * s; ay = ry * s; az = rz * s;

        __half2 p01 = *(const __half2*)(obase + (size_t)k * 100);
        __half2 p23 = *(const __half2*)(obase + (size_t)k * 100 + 2);
        float2 f01 = __half22float2(p01);
        float2 f23 = __half22float2(p23);
        p[0] = ax * f01.x; p[1] = ax * f01.y; p[2]  = ax * f23.x; p[3]  = ax * f23.y;
        p[4] = ay * f01.x; p[5] = ay * f01.y; p[6]  = ay * f23.x; p[7]  = ay * f23.y;
        p[8] = az * f01.x; p[9] = az * f01.y; p[10] = az * f23.x; p[11] = az * f23.y;
    }

#pragma unroll
    for (int i = 0; i < 12; i++) {
#pragma unroll
        for (int sh = 16; sh > 0; sh >>= 1)
            p[i] += __shfl_xor_sync(0xffffffffu, p[i], sh);
    }
    const int warp = tid >> 5, lane = tid & 31;
    if (lane == 0) {
#pragma unroll
        for (int i = 0; i < 12; i++) red[warp * 12 + i] = p[i];
    }
    __syncthreads();
    if (tid < 12)
        t1s[tid] = red[tid] + red[12 + tid] + red[24 + tid] + red[36 + tid];
    __syncthreads();

    if (k < NK) {
        float4 t2;
        t2.x = ax * t1s[0] + ay * t1s[4] + az * t1s[8];
        t2.y = ax * t1s[1] + ay * t1s[5] + az * t1s[9];
        t2.z = ax * t1s[2] + ay * t1s[6] + az * t1s[10];
        t2.w = ax * t1s[3] + ay * t1s[7] + az * t1s[11];
        *(float4*)(t2s + k * 4) = t2;
    }
    __syncthreads();

    if (tid < 100) {
        const int g = tid;
        float a0 = 0.0f, a1 = 0.0f, a2 = 0.0f, a3 = 0.0f;
#pragma unroll 4
        for (int kk = 0; kk < NK; kk++) {
            float  og = __half2float(obase[(size_t)kk * 100 + g]);
            float4 t  = *(const float4*)(t2s + kk * 4);
            a0 = fmaf(og, t.x, a0);
            a1 = fmaf(og, t.y, a1);
            a2 = fmaf(og, t.z, a2);
            a3 = fmaf(og, t.w, a3);
        }
        float4 r; r.x = a0; r.y = a1; r.z = a2; r.w = a3;
        *(float4*)(outp + ((size_t)(b * NCAT + n)) * 400 + g * 4) = r;
    }
}

extern "C" void kernel_launch(void* const* d_in, const int* in_sizes, int n_in,
                              void* d_out, int out_size) {
    const float* coords     = (const float*)d_in[0];
    const int*   atom_types = (const int*)d_in[1];
    const float* W1 = (const float*)d_in[2];
    const float* b1 = (const float*)d_in[3];
    const float* W2 = (const float*)d_in[4];
    const float* b2 = (const float*)d_in[5];
    const float* W3 = (const float*)d_in[6];
    const float* b3 = (const float*)d_in[7];
    float* outp = (float*)d_out;

    prep_pack<<<(NCH * CHW + 255) / 256, 256>>>(W1, b1, W2, b2, W3, b3);
    prep_plan<<<1, 256>>>(atom_types);
    k1_mlp<<<NBLK1, 128>>>(coords, atom_types);
    k2_contract<<<dim3(NCAT, NBATCH), 128>>>(coords, outp);
}